// round 7
// baseline (speedup 1.0000x reference)
#include <cuda_runtime.h>
#include <cuda_fp16.h>
#include <cstdint>

// ---------------- problem constants ----------------
#define MAXN 50000
#define MAXE 800000
#define HID  128
#define JKD  384   // 3*HID
#define NOUT 40

// ---------------- device scratch ----------------
__device__ __align__(16) float g_dinv[MAXN];
__device__ __align__(16) float g_h[(long)MAXN * HID];
__device__ __align__(16) float g_xs[(long)MAXN * JKD];
__device__ int   g_cnt[MAXN];
__device__ int   g_off[MAXN + 1];
__device__ int   g_cur[MAXN];
__device__ int   g_src[MAXE];
__device__ float g_wgt[MAXE];
// fp16 split inputs for tensor-core GEMM
__device__ __align__(16) __half gA_hi[(long)MAXN * 256];
__device__ __align__(16) __half gA_lo[(long)MAXN * 256];
__device__ __align__(16) __half gB_hi[128 * 512];   // W0^T | W1^T | W2^T
__device__ __align__(16) __half gB_lo[128 * 512];

__device__ __forceinline__ uint32_t smem_u32(const void* p) {
    uint32_t a;
    asm("{ .reg .u64 t; cvta.to.shared.u64 t, %1; cvt.u32.u64 %0, t; }" : "=r"(a) : "l"(p));
    return a;
}

// ---------------- CSC build ----------------
__global__ void zero_cnt_kernel(int n) {
    int i = blockIdx.x * blockDim.x + threadIdx.x;
    if (i < n) g_cnt[i] = 0;
}

__global__ void hist_kernel(const int* __restrict__ col, int E) {
    int i = blockIdx.x * blockDim.x + threadIdx.x;
    if (i < E) atomicAdd(&g_cnt[col[i]], 1);
}

// 3-phase single-block scan: local sums -> 1024-scan -> local writeback
__global__ void scan_kernel(int n) {
    __shared__ int ssum[1024];
    int tid = threadIdx.x;
    int chunk = (n + 1023) >> 10;
    int s0 = tid * chunk;
    int s1 = min(s0 + chunk, n);
    int local = 0;
    for (int i = s0; i < s1; i++) local += g_cnt[i];
    ssum[tid] = local;
    __syncthreads();
#pragma unroll
    for (int d = 1; d < 1024; d <<= 1) {
        int t = (tid >= d) ? ssum[tid - d] : 0;
        __syncthreads();
        ssum[tid] += t;
        __syncthreads();
    }
    int run = ssum[tid] - local;  // exclusive prefix of this thread's range
    for (int i = s0; i < s1; i++) { g_off[i] = run; run += g_cnt[i]; }
    if (tid == 1023) g_off[n] = ssum[1023];
}

__global__ void dinv_kernel(int n) {
    int i = blockIdx.x * blockDim.x + threadIdx.x;
    if (i < n) {
        g_dinv[i] = rsqrtf((float)g_cnt[i] + 1.0f);
        g_cur[i] = g_off[i];
    }
}

__global__ void reorder_kernel(const int* __restrict__ row,
                               const int* __restrict__ col, int E) {
    int i = blockIdx.x * blockDim.x + threadIdx.x;
    if (i < E) {
        int r = row[i];
        int c = col[i];
        int pos = atomicAdd(&g_cur[c], 1);
        g_src[pos] = r;
        g_wgt[pos] = g_dinv[r] * g_dinv[c];
    }
}

// ---------------- fp16 split preparation ----------------
__global__ void split_x_kernel(const float* __restrict__ x, int total4) {
    int i = blockIdx.x * blockDim.x + threadIdx.x;
    if (i >= total4) return;
    float4 v = ((const float4*)x)[i];
    __half hx = __float2half_rn(v.x), hy = __float2half_rn(v.y);
    __half hz = __float2half_rn(v.z), hw = __float2half_rn(v.w);
    __half lx = __float2half_rn(v.x - __half2float(hx));
    __half ly = __float2half_rn(v.y - __half2float(hy));
    __half lz = __float2half_rn(v.z - __half2float(hz));
    __half lw = __float2half_rn(v.w - __half2float(hw));
    __half2 h01; h01.x = hx; h01.y = hy;
    __half2 h23; h23.x = hz; h23.y = hw;
    __half2 l01; l01.x = lx; l01.y = ly;
    __half2 l23; l23.x = lz; l23.y = lw;
    ((__half2*)gA_hi)[i * 2 + 0] = h01;
    ((__half2*)gA_hi)[i * 2 + 1] = h23;
    ((__half2*)gA_lo)[i * 2 + 0] = l01;
    ((__half2*)gA_lo)[i * 2 + 1] = l23;
}

__global__ void wtrans_kernel(const float* __restrict__ W, int K, int off) {
    int i = blockIdx.x * blockDim.x + threadIdx.x;
    if (i >= 128 * K) return;
    int n = i / K, k = i % K;
    float a = W[k * 128 + n];
    __half h = __float2half_rn(a);
    gB_hi[off + i] = h;
    gB_lo[off + i] = __float2half_rn(a - __half2float(h));
}

// ---------------- HMMA fp16-split GEMM with cp.async double buffering ----------------
#define SP 72                        // smem halves per row
#define TILE_B (128 * SP * 2)        // 18432 bytes per tile
#define BUFB   (4 * TILE_B)          // one buffer: AH AL BH BL
#define OFF_AH 0
#define OFF_AL (TILE_B)
#define OFF_BH (2 * TILE_B)
#define OFF_BL (3 * TILE_B)
#define HSMEM  (2 * BUFB)            // 147456 bytes

#define CP_COMMIT() asm volatile("cp.async.commit_group;" ::: "memory")

__device__ __forceinline__ void mma16816(float* c, const uint32_t* a, const uint32_t* b) {
    asm volatile(
        "mma.sync.aligned.m16n8k16.row.col.f32.f16.f16.f32 "
        "{%0,%1,%2,%3}, {%4,%5,%6,%7}, {%8,%9}, {%0,%1,%2,%3};"
        : "+f"(c[0]), "+f"(c[1]), "+f"(c[2]), "+f"(c[3])
        : "r"(a[0]), "r"(a[1]), "r"(a[2]), "r"(a[3]), "r"(b[0]), "r"(b[1]));
}

// async stage: 128 rows x 64 halves from gsrc[row][K] into smem tile (stride SP)
__device__ __forceinline__ void stage_tile_async(uint32_t sdst, const __half* __restrict__ gsrc,
                                                 int row0, int Mlim, int K, int k0, int tid) {
#pragma unroll
    for (int p = 0; p < 4; p++) {
        int idx = p * 256 + tid;          // 1024 16B chunks
        int r = idx >> 3;
        int c = idx & 7;
        int gr = row0 + r;
        int ok = (gr < Mlim);
        const void* src = gsrc + (long)(ok ? gr : row0) * K + k0 + c * 8;
        uint32_t dst = sdst + (uint32_t)((r * SP + c * 8) * 2);
        int sz = ok ? 16 : 0;
        asm volatile("cp.async.cg.shared.global [%0], [%1], 16, %2;"
                     :: "r"(dst), "l"(src), "r"(sz) : "memory");
    }
}

__global__ void __launch_bounds__(256, 1)
hgemm_kernel(int M, int K, int boff) {
    extern __shared__ __align__(16) char smem[];
    const uint32_t sb = smem_u32(smem);
    const int tid  = threadIdx.x;
    const int wid  = tid >> 5;
    const int lane = tid & 31;
    const int g = lane >> 2;
    const int t = lane & 3;
    const int wm = (wid >> 2) * 64;
    const int wn = (wid & 3) * 32;
    const int row0 = blockIdx.x * 128;

    float acc[4][4][4];
#pragma unroll
    for (int mi = 0; mi < 4; mi++)
#pragma unroll
        for (int ni = 0; ni < 4; ni++)
#pragma unroll
            for (int j = 0; j < 4; j++) acc[mi][ni][j] = 0.0f;

    const int nchunks = K >> 6;

    // prologue: stage chunk 0 into buffer 0
    stage_tile_async(sb + OFF_AH, gA_hi, row0, M, K, 0, tid);
    stage_tile_async(sb + OFF_AL, gA_lo, row0, M, K, 0, tid);
    stage_tile_async(sb + OFF_BH, gB_hi + boff, 0, 128, K, 0, tid);
    stage_tile_async(sb + OFF_BL, gB_lo + boff, 0, 128, K, 0, tid);
    CP_COMMIT();

    for (int ch = 0; ch < nchunks; ch++) {
        const uint32_t bufo = (uint32_t)(ch & 1) * BUFB;
        if (ch + 1 < nchunks) {
            const uint32_t nb = (uint32_t)((ch + 1) & 1) * BUFB;
            const int k1 = (ch + 1) << 6;
            stage_tile_async(sb + nb + OFF_AH, gA_hi, row0, M, K, k1, tid);
            stage_tile_async(sb + nb + OFF_AL, gA_lo, row0, M, K, k1, tid);
            stage_tile_async(sb + nb + OFF_BH, gB_hi + boff, 0, 128, K, k1, tid);
            stage_tile_async(sb + nb + OFF_BL, gB_lo + boff, 0, 128, K, k1, tid);
            CP_COMMIT();
            asm volatile("cp.async.wait_group 1;" ::: "memory");
        } else {
            asm volatile("cp.async.wait_group 0;" ::: "memory");
        }
        __syncthreads();

        const __half* sAh = (const __half*)(smem + bufo + OFF_AH);
        const __half* sAl = (const __half*)(smem + bufo + OFF_AL);
        const __half* sBh = (const __half*)(smem + bufo + OFF_BH);
        const __half* sBl = (const __half*)(smem + bufo + OFF_BL);

#pragma unroll
        for (int ks = 0; ks < 4; ks++) {
            const int kb = ks * 16;
            uint32_t ah[4][4], al[4][4], bh[4][2], bl[4][2];
#pragma unroll
            for (int mi = 0; mi < 4; mi++) {
                int r0 = (wm + mi * 16 + g) * SP + kb + 2 * t;
                int r1 = r0 + 8 * SP;
                ah[mi][0] = *(const uint32_t*)(sAh + r0);
                ah[mi][1] = *(const uint32_t*)(sAh + r1);
                ah[mi][2] = *(const uint32_t*)(sAh + r0 + 8);
                ah[mi][3] = *(const uint32_t*)(sAh + r1 + 8);
                al[mi][0] = *(const uint32_t*)(sAl + r0);
                al[mi][1] = *(const uint32_t*)(sAl + r1);
                al[mi][2] = *(const uint32_t*)(sAl + r0 + 8);
                al[mi][3] = *(const uint32_t*)(sAl + r1 + 8);
            }
#pragma unroll
            for (int ni = 0; ni < 4; ni++) {
                int rb = (wn + ni * 8 + g) * SP + kb + 2 * t;
                bh[ni][0] = *(const uint32_t*)(sBh + rb);
                bh[ni][1] = *(const uint32_t*)(sBh + rb + 8);
                bl[ni][0] = *(const uint32_t*)(sBl + rb);
                bl[ni][1] = *(const uint32_t*)(sBl + rb + 8);
            }
#pragma unroll
            for (int mi = 0; mi < 4; mi++)
#pragma unroll
                for (int ni = 0; ni < 4; ni++) {
                    mma16816(acc[mi][ni], ah[mi], bh[ni]);
                    mma16816(acc[mi][ni], ah[mi], bl[ni]);
                    mma16816(acc[mi][ni], al[mi], bh[ni]);
                }
        }
        __syncthreads();
    }

#pragma unroll
    for (int mi = 0; mi < 4; mi++) {
        int r0 = row0 + wm + mi * 16 + g;
        int r1 = r0 + 8;
#pragma unroll
        for (int ni = 0; ni < 4; ni++) {
            int cc = wn + ni * 8 + 2 * t;
            if (r0 < M) *(float2*)&g_h[(long)r0 * 128 + cc] = make_float2(acc[mi][ni][0], acc[mi][ni][1]);
            if (r1 < M) *(float2*)&g_h[(long)r1 * 128 + cc] = make_float2(acc[mi][ni][2], acc[mi][ni][3]);
        }
    }
}

// ---------------- gather: xs[c, off:+128] = relu(sum_in h[r]*w + h[c]*d2 + b) ----------------
__global__ __launch_bounds__(256)
void gather_kernel(const float* __restrict__ b, int xs_off, int n, int emit_fp16) {
    int warp = (blockIdx.x * blockDim.x + threadIdx.x) >> 5;
    if (warp >= n) return;
    int lane = threadIdx.x & 31;
    int c = warp;

    float d = g_dinv[c];
    float d2 = d * d;
    float4 self = ((const float4*)g_h)[(long)c * 32 + lane];
    float4 bb = ((const float4*)b)[lane];
    float4 acc;
    acc.x = fmaf(self.x, d2, bb.x);
    acc.y = fmaf(self.y, d2, bb.y);
    acc.z = fmaf(self.z, d2, bb.z);
    acc.w = fmaf(self.w, d2, bb.w);

    int e = g_off[c];
    const int end = g_off[c + 1];

    // 8-deep unroll: batch index/weight loads, then 8 independent float4 gathers
    for (; e + 8 <= end; e += 8) {
        int rr[8];
        float ww[8];
#pragma unroll
        for (int j = 0; j < 8; j++) { rr[j] = g_src[e + j]; ww[j] = g_wgt[e + j]; }
        float4 vv[8];
#pragma unroll
        for (int j = 0; j < 8; j++) vv[j] = ((const float4*)g_h)[(long)rr[j] * 32 + lane];
#pragma unroll
        for (int j = 0; j < 8; j++) {
            acc.x = fmaf(vv[j].x, ww[j], acc.x);
            acc.y = fmaf(vv[j].y, ww[j], acc.y);
            acc.z = fmaf(vv[j].z, ww[j], acc.z);
            acc.w = fmaf(vv[j].w, ww[j], acc.w);
        }
    }
    for (; e < end; e++) {
        int r = g_src[e];
        float w = g_wgt[e];
        float4 v = ((const float4*)g_h)[(long)r * 32 + lane];
        acc.x = fmaf(v.x, w, acc.x); acc.y = fmaf(v.y, w, acc.y);
        acc.z = fmaf(v.z, w, acc.z); acc.w = fmaf(v.w, w, acc.w);
    }

    float4 o;
    o.x = fmaxf(acc.x, 0.f);
    o.y = fmaxf(acc.y, 0.f);
    o.z = fmaxf(acc.z, 0.f);
    o.w = fmaxf(acc.w, 0.f);
    *(float4*)&g_xs[(long)c * JKD + xs_off + lane * 4] = o;

    if (emit_fp16) {
        __half hx = __float2half_rn(o.x), hy = __float2half_rn(o.y);
        __half hz = __float2half_rn(o.z), hw = __float2half_rn(o.w);
        __half lx = __float2half_rn(o.x - __half2float(hx));
        __half ly = __float2half_rn(o.y - __half2float(hy));
        __half lz = __float2half_rn(o.z - __half2float(hz));
        __half lw = __float2half_rn(o.w - __half2float(hw));
        __half2 h01; h01.x = hx; h01.y = hy;
        __half2 h23; h23.x = hz; h23.y = hw;
        __half2 l01; l01.x = lx; l01.y = ly;
        __half2 l23; l23.x = lz; l23.y = lw;
        ((__half2*)gA_hi)[(long)c * 64 + lane * 2 + 0] = h01;
        ((__half2*)gA_hi)[(long)c * 64 + lane * 2 + 1] = h23;
        ((__half2*)gA_lo)[(long)c * 64 + lane * 2 + 0] = l01;
        ((__half2*)gA_lo)[(long)c * 64 + lane * 2 + 1] = l23;
    }
}

// ---------------- output GEMM: out[M x 40] = xs[M x 384] @ Wout + bout ----------------
__global__ __launch_bounds__(256)
void outgemm_kernel(const float* __restrict__ Wout, const float* __restrict__ bout,
                    float* __restrict__ out, int M) {
    __shared__ float sX[64][17];
    __shared__ __align__(16) float sW[16 * 40];

    const int tid = threadIdx.x;
    const int rowl = tid >> 2;
    const int cg   = tid & 3;
    const int grow = blockIdx.x * 64 + rowl;

    const int lrow  = tid >> 2;
    const int lcol4 = (tid & 3) * 4;

    float acc[10];
#pragma unroll
    for (int j = 0; j < 10; j++) acc[j] = 0.0f;

    for (int k0 = 0; k0 < JKD; k0 += 16) {
        int xr = blockIdx.x * 64 + lrow;
        float4 xv = make_float4(0.f, 0.f, 0.f, 0.f);
        if (xr < M) xv = *(const float4*)(g_xs + (long)xr * JKD + k0 + lcol4);
        sX[lrow][lcol4 + 0] = xv.x;
        sX[lrow][lcol4 + 1] = xv.y;
        sX[lrow][lcol4 + 2] = xv.z;
        sX[lrow][lcol4 + 3] = xv.w;
        if (tid < 160)
            *(float4*)&sW[tid * 4] = *(const float4*)(Wout + (long)k0 * 40 + tid * 4);
        __syncthreads();

#pragma unroll
        for (int kk = 0; kk < 16; kk++) {
            float a = sX[rowl][kk];
            const float* w = &sW[kk * 40 + cg * 10];
#pragma unroll
            for (int j = 0; j < 10; j++) acc[j] = fmaf(a, w[j], acc[j]);
        }
        __syncthreads();
    }

    if (grow < M) {
#pragma unroll
        for (int j = 0; j < 10; j++)
            out[(long)grow * NOUT + cg * 10 + j] = acc[j] + bout[cg * 10 + j];
    }
}

// ---------------- launch ----------------
extern "C" void kernel_launch(void* const* d_in, const int* in_sizes, int n_in,
                              void* d_out, int out_size) {
    const float* x    = (const float*)d_in[0];
    const int*   ei   = (const int*)d_in[1];   // int32 (JAX x64 disabled)
    const float* W0   = (const float*)d_in[2];
    const float* b0   = (const float*)d_in[3];
    const float* W1   = (const float*)d_in[4];
    const float* b1   = (const float*)d_in[5];
    const float* W2   = (const float*)d_in[6];
    const float* b2   = (const float*)d_in[7];
    const float* Wout = (const float*)d_in[8];
    const float* bout = (const float*)d_in[9];
    float* out = (float*)d_out;

    const int N = in_sizes[0] / 256;
    const int E = in_sizes[1] / 2;
    const int* row = ei;
    const int* col = ei + E;

    cudaFuncSetAttribute(hgemm_kernel, cudaFuncAttributeMaxDynamicSharedMemorySize, HSMEM);

    // ---- fp16 split of x and weights ----
    split_x_kernel<<<(N * 64 + 255) / 256, 256>>>(x, N * 64);
    wtrans_kernel<<<(128 * 256 + 255) / 256, 256>>>(W0, 256, 0);
    wtrans_kernel<<<(128 * 128 + 255) / 256, 256>>>(W1, 128, 128 * 256);
    wtrans_kernel<<<(128 * 128 + 255) / 256, 256>>>(W2, 128, 128 * 256 + 128 * 128);

    // ---- CSC build + gcn_norm ----
    zero_cnt_kernel<<<(N + 255) / 256, 256>>>(N);
    hist_kernel<<<(E + 255) / 256, 256>>>(col, E);
    scan_kernel<<<1, 1024>>>(N);
    dinv_kernel<<<(N + 255) / 256, 256>>>(N);
    reorder_kernel<<<(E + 255) / 256, 256>>>(row, col, E);

    const int gemm_grid = (N + 127) / 128;
    const int gat_grid  = (N + 7) / 8;

    // ---- layer 0 ----
    hgemm_kernel<<<gemm_grid, 256, HSMEM>>>(N, 256, 0);
    gather_kernel<<<gat_grid, 256>>>(b0, 0, N, 1);

    // ---- layer 1 ----
    hgemm_kernel<<<gemm_grid, 256, HSMEM>>>(N, 128, 128 * 256);
    gather_kernel<<<gat_grid, 256>>>(b1, 128, N, 1);

    // ---- layer 2 ----
    hgemm_kernel<<<gemm_grid, 256, HSMEM>>>(N, 128, 128 * 256 + 128 * 128);
    gather_kernel<<<gat_grid, 256>>>(b2, 256, N, 0);

    // ---- JK output ----
    outgemm_kernel<<<(N + 63) / 64, 256>>>(Wout, bout, out, N);
}